// round 15
// baseline (speedup 1.0000x reference)
#include <cuda_runtime.h>
#include <cstdint>

#define NN   32
#define CC   64
#define HH   112
#define WW   112
#define HW   (HH*WW)        // 12544
#define OO   64
#define TAPS 9
#define WSTRIDE 10          // padded weight row (16B-aligned rows: 80 bytes)
#define OB   32             // output channels per block

typedef unsigned long long u64;
typedef unsigned int uint;

// Static device scratch (no allocation)
__device__ __align__(16) u64 g_packed[NN * HW];        // bit c = (A[n][c][y][x] > 0)
__device__ __align__(16) u64 g_wbits[OO * WSTRIDE];    // padded rows of 10

// Carry-save adder, forced instruction selection: XOR3 (0x96) + MAJ3 (0xE8),
// exactly 4 LOP3.32 per u64.
__device__ __forceinline__ void csa(u64& s, u64& c, u64 x, u64 y, u64 z) {
    uint xl = (uint)x, xh = (uint)(x >> 32);
    uint yl = (uint)y, yh = (uint)(y >> 32);
    uint zl = (uint)z, zh = (uint)(z >> 32);
    uint sl, sh, cl, ch;
    asm("lop3.b32 %0, %1, %2, %3, 0x96;" : "=r"(sl) : "r"(xl), "r"(yl), "r"(zl));
    asm("lop3.b32 %0, %1, %2, %3, 0x96;" : "=r"(sh) : "r"(xh), "r"(yh), "r"(zh));
    asm("lop3.b32 %0, %1, %2, %3, 0xE8;" : "=r"(cl) : "r"(xl), "r"(yl), "r"(zl));
    asm("lop3.b32 %0, %1, %2, %3, 0xE8;" : "=r"(ch) : "r"(xh), "r"(yh), "r"(zh));
    s = (u64)sl | ((u64)sh << 32);
    c = (u64)cl | ((u64)ch << 32);
}

// ---------------------------------------------------------------------------
// Kernel 1: pack weights. One warp per (o,t); lane covers channels lane, lane+32.
// ---------------------------------------------------------------------------
__global__ void pack_weights_kernel(const float* __restrict__ w) {
    int wid  = blockIdx.x * (blockDim.x >> 5) + (threadIdx.x >> 5);
    int lane = threadIdx.x & 31;
    if (wid >= OO * TAPS) return;
    int o = wid / TAPS, t = wid % TAPS;
    float v0 = w[(o * CC + lane) * TAPS + t];
    float v1 = w[(o * CC + lane + 32) * TAPS + t];
    unsigned b0 = __ballot_sync(0xFFFFFFFFu, v0 > 0.0f);
    unsigned b1 = __ballot_sync(0xFFFFFFFFu, v1 > 0.0f);
    if (lane == 0)
        g_wbits[o * WSTRIDE + t] = (u64)b0 | ((u64)b1 << 32);
}

// ---------------------------------------------------------------------------
// Kernel 2: pack activations. 4 consecutive pixels/thread via float4 loads.
// ---------------------------------------------------------------------------
__global__ void pack_act_kernel(const float* __restrict__ act) {
    int tidg = blockIdx.x * blockDim.x + threadIdx.x;
    int p0   = tidg * 4;
    int n    = p0 / HW;
    int p    = p0 - n * HW;

    const float* base = act + (long)(n * CC) * HW + p;
    u64 w0 = 0, w1 = 0, w2 = 0, w3 = 0;
#pragma unroll
    for (int c = 0; c < CC; c++) {
        float4 v = *(const float4*)(base + (long)c * HW);
        w0 |= (u64)(v.x > 0.0f) << c;
        w1 |= (u64)(v.y > 0.0f) << c;
        w2 |= (u64)(v.z > 0.0f) << c;
        w3 |= (u64)(v.w > 0.0f) << c;
    }
    ulonglong2* dst = (ulonglong2*)(g_packed + p0);
    dst[0] = make_ulonglong2(w0, w1);
    dst[1] = make_ulonglong2(w2, w3);
}

// ---------------------------------------------------------------------------
// Kernel 3: binary conv, 5-CSA tree (8 POPC32/output), fused border,
// fix table built in-prologue from smem weights.
// Flat block 224 (7 full warps); OB=32; grid (14, 32, 2); 4 blocks/SM.
// Sum identity: sum popc(x_t) = popc(s4)+2popc(c4)+2popc(s3)+4popc(c3).
// ---------------------------------------------------------------------------
__global__ __launch_bounds__(224, 4)
void bconv_kernel(float* __restrict__ out) {
    __shared__ __align__(16) u64 ws[OB * WSTRIDE];
    __shared__ float fix_s[16 * OB];

    int obase = blockIdx.z * OB;
    int tid = threadIdx.x;
    for (int i = tid; i < OB * WSTRIDE; i += 224)
        ws[i] = g_wbits[obase * WSTRIDE + i];
    __syncthreads();

    // Build border fix table from ws: entry (m, o): 2*sum_{invalid} popc - 64*nmiss
    for (int i = tid; i < 16 * OB; i += 224) {
        int m = i / OB, o = i % OB;
        bool T = m & 1, B = m & 2, L = m & 4, R = m & 8;
        int corr = 0, nmiss = 0;
#pragma unroll
        for (int t = 0; t < 9; t++) {
            int r = t / 3, c = t % 3;
            bool inv = (T && r == 0) || (B && r == 2) || (L && c == 0) || (R && c == 2);
            if (inv) {
                corr += __popcll(ws[o * WSTRIDE + t]);
                nmiss++;
            }
        }
        fix_s[i] = (float)(2 * corr - CC * nmiss);
    }
    __syncthreads();

    int xq = tid % 28;
    int x0 = xq * 4;
    int y  = blockIdx.x * 8 + tid / 28;
    int n  = blockIdx.y;

    const u64* pb = g_packed + (long)n * HW;

    // 3x6 window, zero for OOB (corrected via fix table)
    u64 a[3][6];
#pragma unroll
    for (int r = 0; r < 3; r++) {
        int yy = y - 1 + r;
        bool rv = (unsigned)yy < (unsigned)HH;
        const u64* row = pb + yy * WW;
#pragma unroll
        for (int c = 0; c < 6; c++) {
            int xx = x0 - 1 + c;
            bool v = rv && ((unsigned)xx < (unsigned)WW);
            a[r][c] = v ? row[xx] : 0ull;
        }
    }

    // Border class masks (per output pixel)
    int m_y = (y == 0 ? 1 : 0) | (y == 111 ? 2 : 0);
    int m0  = m_y | (x0 == 0 ? 4 : 0);
    int m3  = m_y | (x0 == 108 ? 8 : 0);
    bool anyb = (m0 | m3) != 0;

    const float MAGIC_SUB = 16777792.0f;  // 2^24 + 576

    float* ob = out + ((long)(n * OO + obase)) * HW + y * WW + x0;

#pragma unroll 2
    for (int o = 0; o < OB; o++) {
        const ulonglong2* wr2 = (const ulonglong2*)(ws + o * WSTRIDE);
        ulonglong2 wp0 = wr2[0], wp1 = wr2[1], wp2 = wr2[2], wp3 = wr2[3];
        u64 wv[9] = { wp0.x, wp0.y, wp1.x, wp1.y, wp2.x, wp2.y, wp3.x, wp3.y,
                      ws[o * WSTRIDE + 8] };

        float4 res;
#pragma unroll
        for (int px = 0; px < 4; px++) {
            u64 s0, s1, s2, s3, s4, c0, c1, c2, c3, c4;
            csa(s0, c0, a[0][px] ^ wv[0], a[0][px + 1] ^ wv[1], a[0][px + 2] ^ wv[2]);
            csa(s1, c1, a[1][px] ^ wv[3], a[1][px + 1] ^ wv[4], a[1][px + 2] ^ wv[5]);
            csa(s2, c2, a[2][px] ^ wv[6], a[2][px + 1] ^ wv[7], a[2][px + 2] ^ wv[8]);
            csa(s3, c3, c0, c1, c2);
            csa(s4, c4, s0, s1, s2);

            int acc = __popcll(s4) + 2 * (__popcll(c4) + __popcll(s3))
                    + 4 * __popcll(c3);
            float v = fmaf(-2.0f, __int_as_float(0x4B000000 | acc), MAGIC_SUB);
            if (px == 0) res.x = v;
            else if (px == 1) res.y = v;
            else if (px == 2) res.z = v;
            else res.w = v;
        }

        if (anyb) {
            res.x += fix_s[m0  * OB + o];
            res.y += fix_s[m_y * OB + o];
            res.z += fix_s[m_y * OB + o];
            res.w += fix_s[m3  * OB + o];
        }

        *(float4*)(ob + (long)o * HW) = res;
    }
}

// ---------------------------------------------------------------------------
extern "C" void kernel_launch(void* const* d_in, const int* in_sizes, int n_in,
                              void* d_out, int out_size) {
    const float* act = (const float*)d_in[0];   // [32,64,112,112]
    const float* w   = (const float*)d_in[1];   // [64*64*9, 1]
    float* out       = (float*)d_out;           // [32,64,112,112]

    pack_weights_kernel<<<72, 256>>>(w);
    pack_act_kernel<<<(NN * HW / 4) / 128, 128>>>(act);

    dim3 grid(HH / 8, NN, 2);
    bconv_kernel<<<grid, 224>>>(out);
}